// round 1
// baseline (speedup 1.0000x reference)
#include <cuda_runtime.h>
#include <math.h>

#define LATD 256
#define TMROWS 64
#define KC 32
#define NJOINT 43
#define BT 6272

// dynamic shared layout (floats):
//   Hs  [256][64]   = 16384
//   W2s [32][256]   =  8192
//   w1s [3][256]    =   768
//   b1s [256]       =   256
//   b2s [256]       =   256
#define SMEM_FLOATS (LATD*TMROWS + KC*LATD + 3*LATD + LATD + LATD)
#define SMEM_BYTES  (SMEM_FLOATS * 4)

__global__ void __launch_bounds__(256, 2)
me_kernel(const float* __restrict__ x,
          const float* __restrict__ W1_3, const float* __restrict__ b1_3,
          const float* __restrict__ W2_3, const float* __restrict__ b2_3,
          const float* __restrict__ W1_2, const float* __restrict__ b1_2,
          const float* __restrict__ W2_2, const float* __restrict__ b2_2,
          const float* __restrict__ W1_1, const float* __restrict__ b1_1,
          const float* __restrict__ W2_1, const float* __restrict__ b2_1,
          float* __restrict__ out)
{
    extern __shared__ float smem[];
    float* Hs  = smem;                     // [256][64] transposed H
    float* W2s = Hs  + LATD * TMROWS;      // [32][256]
    float* w1s = W2s + KC * LATD;          // [3][256]
    float* b1s = w1s + 3 * LATD;           // [256]
    float* b2s = b1s + LATD;               // [256]

    const int t  = threadIdx.x;
    const int j  = blockIdx.y;             // joint 0..42
    const int m0 = blockIdx.x * TMROWS;    // row tile base in [0, 6272)

    // ---- resolve per-joint parameter pointers ----
    const float *W1, *b1, *W2, *b2;
    int d, xoff;
    if (j < 13) {
        d = 3; xoff = j * 3;
        W1 = W1_3 + j * 3 * LATD;  b1 = b1_3 + j * LATD;
        W2 = W2_3 + (size_t)j * LATD * LATD;  b2 = b2_3 + j * LATD;
    } else if (j < 23) {
        int jj = j - 13;
        d = 2; xoff = 39 + jj * 2;
        W1 = W1_2 + jj * 2 * LATD; b1 = b1_2 + jj * LATD;
        W2 = W2_2 + (size_t)jj * LATD * LATD; b2 = b2_2 + jj * LATD;
    } else {
        int jj = j - 23;
        d = 1; xoff = 59 + jj;
        W1 = W1_1 + jj * LATD;     b1 = b1_1 + jj * LATD;
        W2 = W2_1 + (size_t)jj * LATD * LATD; b2 = b2_1 + jj * LATD;
    }

    // ---- preload small per-joint params (t covers all 256 lats) ----
    b1s[t] = b1[t];
    b2s[t] = b2[t];
    #pragma unroll
    for (int i = 0; i < 3; ++i)
        w1s[i * LATD + t] = (i < d) ? W1[i * LATD + t] : 0.0f;

    // ---- per-thread x row (row = t % 64, reused across 64 lats) ----
    const int row = t & 63;
    float xr[3];
    {
        const float* xp = x + (size_t)(m0 + row) * 79 + xoff;
        #pragma unroll
        for (int i = 0; i < 3; ++i) xr[i] = (i < d) ? xp[i] : 0.0f;
    }
    __syncthreads();

    // ---- phase 1: H = gelu_tanh(x*W1 + b1), stored transposed Hs[lat][row] ----
    // thread-subset s = t>>6 handles lats == s (mod 4); rows within warp are
    // consecutive -> conflict-free STS.
    {
        const int sub = t >> 6;
        #pragma unroll 8
        for (int i = 0; i < 64; ++i) {
            int lat = (i << 2) + sub;
            float h = b1s[lat]
                    + xr[0] * w1s[lat]
                    + xr[1] * w1s[LATD + lat]
                    + xr[2] * w1s[2 * LATD + lat];
            float c = 0.7978845608028654f * (h + 0.044715f * h * h * h);
            float g = 0.5f * h * (1.0f + tanhf(c));
            Hs[lat * TMROWS + row] = g;
        }
    }

    // ---- phase 2: O = H @ W2, 8x8 register blocking ----
    const int tx = t & 31;     // cols {tx*4..tx*4+3, 128+tx*4..+3}
    const int ty = t >> 5;     // rows ty*8 .. ty*8+7

    float acc[8][8];
    #pragma unroll
    for (int r = 0; r < 8; ++r)
        #pragma unroll
        for (int c = 0; c < 8; ++c) acc[r][c] = 0.0f;

    const float4* W2g4 = (const float4*)W2;
    float4* W2s4 = (float4*)W2s;

    for (int kc = 0; kc < LATD; kc += KC) {
        __syncthreads();   // previous chunk consumed (and phase-1 Hs ready on first iter)
        #pragma unroll
        for (int i = 0; i < 8; ++i)
            W2s4[i * 256 + t] = W2g4[kc * 64 + i * 256 + t];
        __syncthreads();

        #pragma unroll 8
        for (int kk = 0; kk < KC; ++kk) {
            const float* hp = Hs + (kc + kk) * TMROWS + ty * 8;
            float4 a0 = *(const float4*)hp;          // warp-broadcast
            float4 a1 = *(const float4*)(hp + 4);
            const float* wp = W2s + kk * LATD + tx * 4;
            float4 q0 = *(const float4*)wp;          // conflict-free contiguous
            float4 q1 = *(const float4*)(wp + 128);

            float a[8]  = {a0.x, a0.y, a0.z, a0.w, a1.x, a1.y, a1.z, a1.w};
            float bv[8] = {q0.x, q0.y, q0.z, q0.w, q1.x, q1.y, q1.z, q1.w};
            #pragma unroll
            for (int r = 0; r < 8; ++r)
                #pragma unroll
                for (int c = 0; c < 8; ++c)
                    acc[r][c] += a[r] * bv[c];
        }
    }

    // ---- epilogue: add b2, write out [BT, 43, 256] ----
    #pragma unroll
    for (int r = 0; r < 8; ++r) {
        size_t grow = (size_t)(m0 + ty * 8 + r);
        float* op = out + (grow * NJOINT + j) * LATD;
        float4 v0, v1;
        v0.x = acc[r][0] + b2s[tx * 4 + 0];
        v0.y = acc[r][1] + b2s[tx * 4 + 1];
        v0.z = acc[r][2] + b2s[tx * 4 + 2];
        v0.w = acc[r][3] + b2s[tx * 4 + 3];
        v1.x = acc[r][4] + b2s[128 + tx * 4 + 0];
        v1.y = acc[r][5] + b2s[128 + tx * 4 + 1];
        v1.z = acc[r][6] + b2s[128 + tx * 4 + 2];
        v1.w = acc[r][7] + b2s[128 + tx * 4 + 3];
        *(float4*)(op + tx * 4)       = v0;
        *(float4*)(op + 128 + tx * 4) = v1;
    }
}

extern "C" void kernel_launch(void* const* d_in, const int* in_sizes, int n_in,
                              void* d_out, int out_size)
{
    (void)in_sizes; (void)n_in; (void)out_size;
    cudaFuncSetAttribute(me_kernel,
                         cudaFuncAttributeMaxDynamicSharedMemorySize, SMEM_BYTES);

    const float* x    = (const float*)d_in[0];
    const float* W1_3 = (const float*)d_in[1];
    const float* b1_3 = (const float*)d_in[2];
    const float* W2_3 = (const float*)d_in[3];
    const float* b2_3 = (const float*)d_in[4];
    const float* W1_2 = (const float*)d_in[5];
    const float* b1_2 = (const float*)d_in[6];
    const float* W2_2 = (const float*)d_in[7];
    const float* b2_2 = (const float*)d_in[8];
    const float* W1_1 = (const float*)d_in[9];
    const float* b1_1 = (const float*)d_in[10];
    const float* W2_1 = (const float*)d_in[11];
    const float* b2_1 = (const float*)d_in[12];

    dim3 grid(BT / TMROWS, NJOINT);   // 98 x 43
    me_kernel<<<grid, 256, SMEM_BYTES>>>(
        x, W1_3, b1_3, W2_3, b2_3,
        W1_2, b1_2, W2_2, b2_2,
        W1_1, b1_1, W2_1, b2_1,
        (float*)d_out);
}

// round 3
// speedup vs baseline: 2.0396x; 2.0396x over previous
#include <cuda_runtime.h>
#include <cuda_bf16.h>
#include <cstdint>

#define LATD 256
#define MT 128
#define NJOINT 43
#define BT 6272
#define XDIM 79

// smem layout (bytes)
#define SMEM_A_HI 0         // [128 rows][512B]  swizzled bf16 H hi
#define SMEM_A_LO 65536     // H lo
#define SMEM_B    131072    // 2 buffers x 32768 (hi 16K + lo 16K each)
#define SMEM_TOTAL 196608

// pre-split, pre-swizzled W2 (bf16 hi/lo) laid out as the exact smem image:
// g_B[(j*8 + chunk)*32768]: bytes 0..16383 = hi (32 k-rows x 512B), 16384.. = lo
__device__ unsigned char g_B[(size_t)NJOINT * 8 * 32768];

// ---------------- helpers ----------------
__device__ __forceinline__ uint32_t smem_u32(const void* p) {
    uint32_t a;
    asm("{ .reg .u64 t; cvta.to.shared.u64 t, %1; cvt.u32.u64 %0, t; }" : "=r"(a) : "l"(p));
    return a;
}
__device__ __forceinline__ void ldsm4(uint32_t* r, uint32_t addr) {
    asm volatile("ldmatrix.sync.aligned.m8n8.x4.shared.b16 {%0,%1,%2,%3}, [%4];"
        : "=r"(r[0]), "=r"(r[1]), "=r"(r[2]), "=r"(r[3]) : "r"(addr));
}
__device__ __forceinline__ void ldsm4t(uint32_t* r, uint32_t addr) {
    asm volatile("ldmatrix.sync.aligned.m8n8.x4.trans.shared.b16 {%0,%1,%2,%3}, [%4];"
        : "=r"(r[0]), "=r"(r[1]), "=r"(r[2]), "=r"(r[3]) : "r"(addr));
}
__device__ __forceinline__ void mma_bf16(float* d, const uint32_t* a, const uint32_t* b) {
    asm volatile("mma.sync.aligned.m16n8k16.row.col.f32.bf16.bf16.f32 "
        "{%0,%1,%2,%3}, {%4,%5,%6,%7}, {%8,%9}, {%0,%1,%2,%3};"
        : "+f"(d[0]), "+f"(d[1]), "+f"(d[2]), "+f"(d[3])
        : "r"(a[0]), "r"(a[1]), "r"(a[2]), "r"(a[3]), "r"(b[0]), "r"(b[1]));
}
__device__ __forceinline__ void cp16(uint32_t dst, const void* src) {
    asm volatile("cp.async.cg.shared.global [%0], [%1], 16;" :: "r"(dst), "l"(src) : "memory");
}
#define CP_COMMIT() asm volatile("cp.async.commit_group;" ::: "memory")
#define CP_WAIT(n)  asm volatile("cp.async.wait_group %0;" :: "n"(n) : "memory")

__device__ __forceinline__ void split_bf16(float v, unsigned short& hi, unsigned short& lo) {
    __nv_bfloat16 h = __float2bfloat16(v);
    hi = __bfloat16_as_ushort(h);
    lo = __bfloat16_as_ushort(__float2bfloat16(v - __bfloat162float(h)));
}

// ---------------- W2 pre-split prologue ----------------
// grid = NJOINT*8 blocks (j*8 + chunk), 256 threads
__global__ void __launch_bounds__(256)
w2_split_kernel(const float* __restrict__ W2_3, const float* __restrict__ W2_2,
                const float* __restrict__ W2_1)
{
    const int blk = blockIdx.x;
    const int j = blk >> 3, c = blk & 7;
    const float* W2;
    if (j < 13)      W2 = W2_3 + (size_t)j * LATD * LATD;
    else if (j < 23) W2 = W2_2 + (size_t)(j - 13) * LATD * LATD;
    else             W2 = W2_1 + (size_t)(j - 23) * LATD * LATD;

    unsigned char* dst = g_B + (size_t)blk * 32768;
    const int t = threadIdx.x;
    #pragma unroll
    for (int q = 0; q < 4; ++q) {
        int pid = t + q * 256;
        int kr = pid >> 5;          // 0..31  (k within chunk)
        int nb = pid & 31;          // 0..31  (8-col block)
        const float* src = W2 + (size_t)(c * 32 + kr) * LATD + nb * 8;
        float4 v0 = *(const float4*)src;
        float4 v1 = *(const float4*)(src + 4);
        unsigned short h[8], l[8];
        split_bf16(v0.x, h[0], l[0]); split_bf16(v0.y, h[1], l[1]);
        split_bf16(v0.z, h[2], l[2]); split_bf16(v0.w, h[3], l[3]);
        split_bf16(v1.x, h[4], l[4]); split_bf16(v1.y, h[5], l[5]);
        split_bf16(v1.z, h[6], l[6]); split_bf16(v1.w, h[7], l[7]);
        uint4 ph, pl;
        ph.x = h[0] | ((uint32_t)h[1] << 16); ph.y = h[2] | ((uint32_t)h[3] << 16);
        ph.z = h[4] | ((uint32_t)h[5] << 16); ph.w = h[6] | ((uint32_t)h[7] << 16);
        pl.x = l[0] | ((uint32_t)l[1] << 16); pl.y = l[2] | ((uint32_t)l[3] << 16);
        pl.z = l[4] | ((uint32_t)l[5] << 16); pl.w = l[6] | ((uint32_t)l[7] << 16);
        uint32_t off = (uint32_t)(kr * 512) + (uint32_t)((nb ^ (kr & 7)) << 4);
        *(uint4*)(dst + off)         = ph;
        *(uint4*)(dst + 16384 + off) = pl;
    }
}

// ---------------- main kernel ----------------
__global__ void __launch_bounds__(256, 1)
me_hmma_kernel(const float* __restrict__ x,
               const float* __restrict__ W1_3, const float* __restrict__ b1_3,
               const float* __restrict__ b2_3,
               const float* __restrict__ W1_2, const float* __restrict__ b1_2,
               const float* __restrict__ b2_2,
               const float* __restrict__ W1_1, const float* __restrict__ b1_1,
               const float* __restrict__ b2_1,
               float* __restrict__ out)
{
    extern __shared__ char smem[];
    const uint32_t sb  = smem_u32(smem);
    const uint32_t sbB = sb + SMEM_B;
    const int t = threadIdx.x;
    const int lane = t & 31, wid = t >> 5;
    const int j = blockIdx.y;
    const int m0 = blockIdx.x * MT;

    // per-joint meta
    int d, xoff;
    const float *W1, *b1, *b2;
    if (j < 13)      { d = 3; xoff = j * 3;
        W1 = W1_3 + j * 3 * LATD; b1 = b1_3 + j * LATD; b2 = b2_3 + j * LATD; }
    else if (j < 23) { int jj = j - 13; d = 2; xoff = 39 + jj * 2;
        W1 = W1_2 + jj * 2 * LATD; b1 = b1_2 + jj * LATD; b2 = b2_2 + jj * LATD; }
    else             { int jj = j - 23; d = 1; xoff = 59 + jj;
        W1 = W1_1 + jj * LATD;     b1 = b1_1 + jj * LATD; b2 = b2_1 + jj * LATD; }

    const unsigned char* gB = g_B + (size_t)j * 8 * 32768;

    // ---- prefetch B chunks 0,1 (overlaps phase 1) ----
    {
        uint32_t dst0 = sbB + t * 16;
        const unsigned char* s0 = gB + t * 16;
        #pragma unroll
        for (int q = 0; q < 8; ++q) cp16(dst0 + q * 4096, s0 + q * 4096);
        CP_COMMIT();
        uint32_t dst1 = sbB + 32768 + t * 16;
        const unsigned char* s1 = gB + 32768 + t * 16;
        #pragma unroll
        for (int q = 0; q < 8; ++q) cp16(dst1 + q * 4096, s1 + q * 4096);
        CP_COMMIT();
    }

    // ---- phase 1: H = gelu_tanh(x*W1 + b1) -> swizzled bf16 hi/lo A tiles ----
    // lane owns k = lane*8..lane*8+7 (fixed); warp owns rows (t>>5) + it*8
    {
        const int kbase = lane * 8;
        float w1r[3][8], b1r[8];
        #pragma unroll
        for (int e = 0; e < 8; ++e) b1r[e] = b1[kbase + e];
        #pragma unroll
        for (int i = 0; i < 3; ++i)
            #pragma unroll
            for (int e = 0; e < 8; ++e)
                w1r[i][e] = (i < d) ? W1[i * LATD + kbase + e] : 0.0f;

        #pragma unroll 4
        for (int it = 0; it < 16; ++it) {
            const int m = (t >> 5) + it * 8;
            const float* xp = x + (size_t)(m0 + m) * XDIM + xoff;
            float x0 = xp[0];
            float x1 = (d > 1) ? xp[1] : 0.0f;
            float x2 = (d > 2) ? xp[2] : 0.0f;
            uint32_t ph[4], pl[4];
            #pragma unroll
            for (int e2 = 0; e2 < 4; ++e2) {
                unsigned short hh[2], ll[2];
                #pragma unroll
                for (int e = 0; e < 2; ++e) {
                    const int e8 = e2 * 2 + e;
                    float h = b1r[e8] + x0 * w1r[0][e8] + x1 * w1r[1][e8] + x2 * w1r[2][e8];
                    float cc = 0.7978845608028654f * fmaf(0.044715f * h, h * h, h);
                    float u = 2.8853900817779268f * cc;       // 2c * log2(e)
                    float te; asm("ex2.approx.f32 %0, %1;" : "=f"(te) : "f"(u));
                    float rc; asm("rcp.approx.f32 %0, %1;" : "=f"(rc) : "f"(te + 1.0f));
                    float g = fmaf(-h, rc, h);                // h*(1 - 1/(e^2c+1)) = gelu
                    split_bf16(g, hh[e], ll[e]);
                }
                ph[e2] = hh[0] | ((uint32_t)hh[1] << 16);
                pl[e2] = ll[0] | ((uint32_t)ll[1] << 16);
            }
            uint32_t addr = (uint32_t)(m * 512) + (uint32_t)((lane ^ (m & 7)) << 4);
            *(uint4*)(smem + SMEM_A_HI + addr) = make_uint4(ph[0], ph[1], ph[2], ph[3]);
            *(uint4*)(smem + SMEM_A_LO + addr) = make_uint4(pl[0], pl[1], pl[2], pl[3]);
        }
    }

    // ---- phase 2: split-bf16 HMMA, warp tile 64x64 (2x4 warp grid) ----
    const int wm = wid >> 2, wn = wid & 3;
    const int M0 = wm * 64, N0 = wn * 64;
    const uint32_t s = lane & 7;
    const uint32_t ktop = lane >> 4;                     // 0/1
    const uint32_t rA = (uint32_t)M0 + ((lane >> 3) & 1) * 8 + s;
    uint32_t aBase[4];
    #pragma unroll
    for (int mf = 0; mf < 4; ++mf) aBase[mf] = sb + (rA + mf * 16) * 512;
    const uint32_t krb = ((lane >> 3) & 1) * 8 + s;      // chunk-local k row (+ ks*16)
    uint32_t cBoff[4];
    #pragma unroll
    for (int nfp = 0; nfp < 4; ++nfp)
        cBoff[nfp] = (((uint32_t)(N0 / 8 + nfp * 2) + ktop) ^ s) << 4;

    float acc[4][8][4];
    #pragma unroll
    for (int mf = 0; mf < 4; ++mf)
        #pragma unroll
        for (int nf = 0; nf < 8; ++nf)
            #pragma unroll
            for (int e = 0; e < 4; ++e) acc[mf][nf][e] = 0.0f;

    #pragma unroll 1
    for (int c = 0; c < 8; ++c) {
        if (c < 7) { CP_WAIT(1); } else { CP_WAIT(0); }
        __syncthreads();
        const uint32_t bufb = sbB + (uint32_t)((c & 1) * 32768);

        #pragma unroll
        for (int ks = 0; ks < 2; ++ks) {
            uint32_t ah[4][4], al[4][4], bh[8][2], bl[8][2];
            const uint32_t koffA = (((uint32_t)(c * 4 + ks * 2) + ktop) ^ s) << 4;
            #pragma unroll
            for (int mf = 0; mf < 4; ++mf) {
                ldsm4(ah[mf], aBase[mf] + koffA);
                ldsm4(al[mf], aBase[mf] + 65536 + koffA);
            }
            const uint32_t rowB = bufb + (krb + ks * 16) * 512;
            #pragma unroll
            for (int nfp = 0; nfp < 4; ++nfp) {
                ldsm4t(&bh[nfp * 2][0], rowB + cBoff[nfp]);
                ldsm4t(&bl[nfp * 2][0], rowB + 16384 + cBoff[nfp]);
            }
            #pragma unroll
            for (int mf = 0; mf < 4; ++mf)
                #pragma unroll
                for (int nf = 0; nf < 8; ++nf)
                    mma_bf16(acc[mf][nf], ah[mf], bh[nf]);
            #pragma unroll
            for (int mf = 0; mf < 4; ++mf)
                #pragma unroll
                for (int nf = 0; nf < 8; ++nf)
                    mma_bf16(acc[mf][nf], ah[mf], bl[nf]);
            #pragma unroll
            for (int mf = 0; mf < 4; ++mf)
                #pragma unroll
                for (int nf = 0; nf < 8; ++nf)
                    mma_bf16(acc[mf][nf], al[mf], bh[nf]);
        }
        __syncthreads();
        if (c + 2 < 8) {
            const int nc = c + 2;
            uint32_t dst = sbB + (uint32_t)((c & 1) * 32768) + t * 16;
            const unsigned char* sp = gB + (size_t)nc * 32768 + t * 16;
            #pragma unroll
            for (int q = 0; q < 8; ++q) cp16(dst + q * 4096, sp + q * 4096);
            CP_COMMIT();
        }
    }

    // ---- epilogue: + b2, write out [BT, 43, 256] ----
    {
        const int colb = 2 * (lane & 3);
        float2 b2v[8];
        #pragma unroll
        for (int nf = 0; nf < 8; ++nf)
            b2v[nf] = *(const float2*)(b2 + N0 + nf * 8 + colb);
        #pragma unroll
        for (int mf = 0; mf < 4; ++mf) {
            const int row = M0 + mf * 16 + (lane >> 2);
            float* p0 = out + ((size_t)(m0 + row) * NJOINT + j) * LATD;
            float* p1 = p0 + (size_t)8 * NJOINT * LATD;
            #pragma unroll
            for (int nf = 0; nf < 8; ++nf) {
                const int col = N0 + nf * 8 + colb;
                float2 v0, v1;
                v0.x = acc[mf][nf][0] + b2v[nf].x;
                v0.y = acc[mf][nf][1] + b2v[nf].y;
                v1.x = acc[mf][nf][2] + b2v[nf].x;
                v1.y = acc[mf][nf][3] + b2v[nf].y;
                *(float2*)(p0 + col) = v0;
                *(float2*)(p1 + col) = v1;
            }
        }
    }
}

extern "C" void kernel_launch(void* const* d_in, const int* in_sizes, int n_in,
                              void* d_out, int out_size)
{
    (void)in_sizes; (void)n_in; (void)out_size;
    cudaFuncSetAttribute(me_hmma_kernel,
                         cudaFuncAttributeMaxDynamicSharedMemorySize, SMEM_TOTAL);

    const float* x    = (const float*)d_in[0];
    const float* W1_3 = (const float*)d_in[1];
    const float* b1_3 = (const float*)d_in[2];
    const float* W2_3 = (const float*)d_in[3];
    const float* b2_3 = (const float*)d_in[4];
    const float* W1_2 = (const float*)d_in[5];
    const float* b1_2 = (const float*)d_in[6];
    const float* W2_2 = (const float*)d_in[7];
    const float* b2_2 = (const float*)d_in[8];
    const float* W1_1 = (const float*)d_in[9];
    const float* b1_1 = (const float*)d_in[10];
    const float* W2_1 = (const float*)d_in[11];
    const float* b2_1 = (const float*)d_in[12];

    w2_split_kernel<<<NJOINT * 8, 256>>>(W2_3, W2_2, W2_1);

    dim3 grid(BT / MT, NJOINT);   // 49 x 43
    me_hmma_kernel<<<grid, 256, SMEM_TOTAL>>>(
        x, W1_3, b1_3, b2_3,
        W1_2, b1_2, b2_2,
        W1_1, b1_1, b2_1,
        (float*)d_out);
}

// round 5
// speedup vs baseline: 2.2552x; 1.1057x over previous
#include <cuda_runtime.h>
#include <cuda_bf16.h>
#include <cstdint>

#define LATD 256
#define MT 64
#define NJOINT 43
#define BT 6272
#define XDIM 79

// smem layout (bytes)
#define SMEM_A_HI 0         // [64 rows][512B] swizzled bf16 H hi = 32768
#define SMEM_A_LO 32768     // H lo
#define SMEM_B    65536     // 2 buffers x 16384 (hi 8K + lo 8K each)
#define SMEM_TOTAL 98304

// pre-split, pre-swizzled W2 (bf16 hi/lo), exact smem image:
// g_B[(j*16 + chunk)*16384]: bytes 0..8191 = hi (16 k-rows x 512B), 8192.. = lo
__device__ unsigned char g_B[(size_t)NJOINT * 16 * 16384];

// ---------------- helpers ----------------
__device__ __forceinline__ uint32_t smem_u32(const void* p) {
    uint32_t a;
    asm("{ .reg .u64 t; cvta.to.shared.u64 t, %1; cvt.u32.u64 %0, t; }" : "=r"(a) : "l"(p));
    return a;
}
__device__ __forceinline__ void ldsm4(uint32_t* r, uint32_t addr) {
    asm volatile("ldmatrix.sync.aligned.m8n8.x4.shared.b16 {%0,%1,%2,%3}, [%4];"
        : "=r"(r[0]), "=r"(r[1]), "=r"(r[2]), "=r"(r[3]) : "r"(addr));
}
__device__ __forceinline__ void ldsm4t(uint32_t* r, uint32_t addr) {
    asm volatile("ldmatrix.sync.aligned.m8n8.x4.trans.shared.b16 {%0,%1,%2,%3}, [%4];"
        : "=r"(r[0]), "=r"(r[1]), "=r"(r[2]), "=r"(r[3]) : "r"(addr));
}
__device__ __forceinline__ void mma_bf16(float* d, const uint32_t* a, const uint32_t* b) {
    asm volatile("mma.sync.aligned.m16n8k16.row.col.f32.bf16.bf16.f32 "
        "{%0,%1,%2,%3}, {%4,%5,%6,%7}, {%8,%9}, {%0,%1,%2,%3};"
        : "+f"(d[0]), "+f"(d[1]), "+f"(d[2]), "+f"(d[3])
        : "r"(a[0]), "r"(a[1]), "r"(a[2]), "r"(a[3]), "r"(b[0]), "r"(b[1]));
}
__device__ __forceinline__ void cp16(uint32_t dst, const void* src) {
    asm volatile("cp.async.cg.shared.global [%0], [%1], 16;" :: "r"(dst), "l"(src) : "memory");
}
#define CP_COMMIT() asm volatile("cp.async.commit_group;" ::: "memory")
#define CP_WAIT(n)  asm volatile("cp.async.wait_group %0;" :: "n"(n) : "memory")

__device__ __forceinline__ void split_bf16(float v, unsigned short& hi, unsigned short& lo) {
    __nv_bfloat16 h = __float2bfloat16(v);
    hi = __bfloat16_as_ushort(h);
    lo = __bfloat16_as_ushort(__float2bfloat16(v - __bfloat162float(h)));
}

// ---------------- W2 pre-split prologue ----------------
// grid = NJOINT*16 blocks (j*16 + chunk), 256 threads
__global__ void __launch_bounds__(256)
w2_split_kernel(const float* __restrict__ W2_3, const float* __restrict__ W2_2,
                const float* __restrict__ W2_1)
{
    const int blk = blockIdx.x;
    const int j = blk >> 4, c = blk & 15;
    const float* W2;
    if (j < 13)      W2 = W2_3 + (size_t)j * LATD * LATD;
    else if (j < 23) W2 = W2_2 + (size_t)(j - 13) * LATD * LATD;
    else             W2 = W2_1 + (size_t)(j - 23) * LATD * LATD;

    unsigned char* dst = g_B + (size_t)blk * 16384;
    const int t = threadIdx.x;
    #pragma unroll
    for (int q = 0; q < 2; ++q) {
        int pid = t + q * 256;       // 0..511
        int kr = pid >> 5;           // 0..15 (k within chunk)
        int nb = pid & 31;           // 0..31 (8-col block)
        const float* src = W2 + (size_t)(c * 16 + kr) * LATD + nb * 8;
        float4 v0 = *(const float4*)src;
        float4 v1 = *(const float4*)(src + 4);
        unsigned short h[8], l[8];
        split_bf16(v0.x, h[0], l[0]); split_bf16(v0.y, h[1], l[1]);
        split_bf16(v0.z, h[2], l[2]); split_bf16(v0.w, h[3], l[3]);
        split_bf16(v1.x, h[4], l[4]); split_bf16(v1.y, h[5], l[5]);
        split_bf16(v1.z, h[6], l[6]); split_bf16(v1.w, h[7], l[7]);
        uint4 ph, pl;
        ph.x = h[0] | ((uint32_t)h[1] << 16); ph.y = h[2] | ((uint32_t)h[3] << 16);
        ph.z = h[4] | ((uint32_t)h[5] << 16); ph.w = h[6] | ((uint32_t)h[7] << 16);
        pl.x = l[0] | ((uint32_t)l[1] << 16); pl.y = l[2] | ((uint32_t)l[3] << 16);
        pl.z = l[4] | ((uint32_t)l[5] << 16); pl.w = l[6] | ((uint32_t)l[7] << 16);
        uint32_t off = (uint32_t)(kr * 512) + (uint32_t)((nb ^ (kr & 7)) << 4);
        *(uint4*)(dst + off)        = ph;
        *(uint4*)(dst + 8192 + off) = pl;
    }
}

// ---------------- main kernel ----------------
__global__ void __launch_bounds__(256, 2)
me_hmma_kernel(const float* __restrict__ x,
               const float* __restrict__ W1_3, const float* __restrict__ b1_3,
               const float* __restrict__ b2_3,
               const float* __restrict__ W1_2, const float* __restrict__ b1_2,
               const float* __restrict__ b2_2,
               const float* __restrict__ W1_1, const float* __restrict__ b1_1,
               const float* __restrict__ b2_1,
               float* __restrict__ out)
{
    extern __shared__ char smem[];
    const uint32_t sb  = smem_u32(smem);
    const uint32_t sbB = sb + SMEM_B;
    const int t = threadIdx.x;
    const int lane = t & 31, wid = t >> 5;
    const int j = blockIdx.y;
    const int m0 = blockIdx.x * MT;

    // per-joint meta
    int d, xoff;
    const float *W1, *b1, *b2;
    if (j < 13)      { d = 3; xoff = j * 3;
        W1 = W1_3 + j * 3 * LATD; b1 = b1_3 + j * LATD; b2 = b2_3 + j * LATD; }
    else if (j < 23) { int jj = j - 13; d = 2; xoff = 39 + jj * 2;
        W1 = W1_2 + jj * 2 * LATD; b1 = b1_2 + jj * LATD; b2 = b2_2 + jj * LATD; }
    else             { int jj = j - 23; d = 1; xoff = 59 + jj;
        W1 = W1_1 + jj * LATD;     b1 = b1_1 + jj * LATD; b2 = b2_1 + jj * LATD; }

    const unsigned char* gB = g_B + (size_t)j * 16 * 16384;

    // ---- prefetch B chunks 0,1 (overlaps phase 1) ----
    {
        uint32_t dst0 = sbB + t * 16;
        const unsigned char* s0 = gB + t * 16;
        #pragma unroll
        for (int q = 0; q < 4; ++q) cp16(dst0 + q * 4096, s0 + q * 4096);
        CP_COMMIT();
        uint32_t dst1 = sbB + 16384 + t * 16;
        const unsigned char* s1 = gB + 16384 + t * 16;
        #pragma unroll
        for (int q = 0; q < 4; ++q) cp16(dst1 + q * 4096, s1 + q * 4096);
        CP_COMMIT();
    }

    // ---- phase 1: H = gelu_tanh(x*W1 + b1) -> swizzled bf16 hi/lo A tiles ----
    {
        const int kbase = lane * 8;
        float w1r[3][8], b1r[8];
        #pragma unroll
        for (int e = 0; e < 8; ++e) b1r[e] = b1[kbase + e];
        #pragma unroll
        for (int i = 0; i < 3; ++i)
            #pragma unroll
            for (int e = 0; e < 8; ++e)
                w1r[i][e] = (i < d) ? W1[i * LATD + kbase + e] : 0.0f;

        #pragma unroll 2
        for (int it = 0; it < 8; ++it) {
            const int m = wid + it * 8;
            const float* xp = x + (size_t)(m0 + m) * XDIM + xoff;
            float x0 = xp[0];
            float x1 = (d > 1) ? xp[1] : 0.0f;
            float x2 = (d > 2) ? xp[2] : 0.0f;
            uint32_t ph[4], pl[4];
            #pragma unroll
            for (int e2 = 0; e2 < 4; ++e2) {
                unsigned short hh[2], ll[2];
                #pragma unroll
                for (int e = 0; e < 2; ++e) {
                    const int e8 = e2 * 2 + e;
                    float h = b1r[e8] + x0 * w1r[0][e8] + x1 * w1r[1][e8] + x2 * w1r[2][e8];
                    float cc = 0.7978845608028654f * fmaf(0.044715f * h, h * h, h);
                    float u = 2.8853900817779268f * cc;       // 2c * log2(e)
                    float te; asm("ex2.approx.f32 %0, %1;" : "=f"(te) : "f"(u));
                    float rc; asm("rcp.approx.f32 %0, %1;" : "=f"(rc) : "f"(te + 1.0f));
                    float g = fmaf(-h, rc, h);                // gelu_tanh(h)
                    split_bf16(g, hh[e], ll[e]);
                }
                ph[e2] = hh[0] | ((uint32_t)hh[1] << 16);
                pl[e2] = ll[0] | ((uint32_t)ll[1] << 16);
            }
            uint32_t addr = (uint32_t)(m * 512) + (uint32_t)((lane ^ (m & 7)) << 4);
            *(uint4*)(smem + SMEM_A_HI + addr) = make_uint4(ph[0], ph[1], ph[2], ph[3]);
            *(uint4*)(smem + SMEM_A_LO + addr) = make_uint4(pl[0], pl[1], pl[2], pl[3]);
        }
    }

    // ---- phase 2: split-bf16 HMMA, warp tile 32x64 (2x4 warp grid) ----
    const int wm = wid >> 2, wn = wid & 3;
    const int M0 = wm * 32, N0 = wn * 64;
    const uint32_t s = lane & 7;
    const uint32_t ktop = lane >> 4;                       // 0/1
    const uint32_t rA = (uint32_t)M0 + ((lane >> 3) & 1) * 8 + s;
    uint32_t aBase[2];
    #pragma unroll
    for (int mf = 0; mf < 2; ++mf) aBase[mf] = sb + (rA + mf * 16) * 512;
    const uint32_t krb = ((lane >> 3) & 1) * 8 + s;        // k row within chunk
    uint32_t cBoff[4];
    #pragma unroll
    for (int nfp = 0; nfp < 4; ++nfp)
        cBoff[nfp] = (((uint32_t)(N0 / 8 + nfp * 2) + ktop) ^ s) << 4;

    // hoist b2 loads (independent of MMA loop; hides L2 latency off the epilogue)
    const int colb = 2 * (lane & 3);
    float2 b2v[8];
    #pragma unroll
    for (int nf = 0; nf < 8; ++nf)
        b2v[nf] = *(const float2*)(b2 + N0 + nf * 8 + colb);

    float acc[2][8][4];
    #pragma unroll
    for (int mf = 0; mf < 2; ++mf)
        #pragma unroll
        for (int nf = 0; nf < 8; ++nf)
            #pragma unroll
            for (int e = 0; e < 4; ++e) acc[mf][nf][e] = 0.0f;

    #pragma unroll 1
    for (int c = 0; c < 16; ++c) {
        if (c < 15) { CP_WAIT(1); } else { CP_WAIT(0); }
        __syncthreads();
        const uint32_t bufb = sbB + (uint32_t)((c & 1) * 16384);

        uint32_t ah[2][4], al[2][4];
        const uint32_t koffA = (((uint32_t)(c * 2) + ktop) ^ s) << 4;
        #pragma unroll
        for (int mf = 0; mf < 2; ++mf) {
            ldsm4(ah[mf], aBase[mf] + koffA);
            ldsm4(al[mf], aBase[mf] + 32768 + koffA);
        }
        const uint32_t rowB = bufb + krb * 512;
        #pragma unroll
        for (int nfp = 0; nfp < 4; ++nfp) {
            uint32_t bh[2][2], bl[2][2];
            ldsm4t(&bh[0][0], rowB + cBoff[nfp]);
            ldsm4t(&bl[0][0], rowB + 8192 + cBoff[nfp]);
            #pragma unroll
            for (int mf = 0; mf < 2; ++mf)
                #pragma unroll
                for (int nn = 0; nn < 2; ++nn) {
                    float* a4 = acc[mf][nfp * 2 + nn];
                    mma_bf16(a4, ah[mf], bh[nn]);
                    mma_bf16(a4, ah[mf], bl[nn]);
                    mma_bf16(a4, al[mf], bh[nn]);
                }
        }
        __syncthreads();
        if (c + 2 < 16) {
            uint32_t dst = bufb + t * 16;
            const unsigned char* sp = gB + (size_t)(c + 2) * 16384 + t * 16;
            #pragma unroll
            for (int q = 0; q < 4; ++q) cp16(dst + q * 4096, sp + q * 4096);
            CP_COMMIT();
        }
    }

    // ---- epilogue: + b2, write out [BT, 43, 256] ----
    {
        #pragma unroll
        for (int mf = 0; mf < 2; ++mf) {
            const int row = M0 + mf * 16 + (lane >> 2);
            float* p0 = out + ((size_t)(m0 + row) * NJOINT + j) * LATD;
            float* p1 = p0 + (size_t)8 * NJOINT * LATD;
            #pragma unroll
            for (int nf = 0; nf < 8; ++nf) {
                const int col = N0 + nf * 8 + colb;
                float2 v0, v1;
                v0.x = acc[mf][nf][0] + b2v[nf].x;
                v0.y = acc[mf][nf][1] + b2v[nf].y;
                v1.x = acc[mf][nf][2] + b2v[nf].x;
                v1.y = acc[mf][nf][3] + b2v[nf].y;
                *(float2*)(p0 + col) = v0;
                *(float2*)(p1 + col) = v1;
            }
        }
    }
}

extern "C" void kernel_launch(void* const* d_in, const int* in_sizes, int n_in,
                              void* d_out, int out_size)
{
    (void)in_sizes; (void)n_in; (void)out_size;
    cudaFuncSetAttribute(me_hmma_kernel,
                         cudaFuncAttributeMaxDynamicSharedMemorySize, SMEM_TOTAL);

    const float* x    = (const float*)d_in[0];
    const float* W1_3 = (const float*)d_in[1];
    const float* b1_3 = (const float*)d_in[2];
    const float* W2_3 = (const float*)d_in[3];
    const float* b2_3 = (const float*)d_in[4];
    const float* W1_2 = (const float*)d_in[5];
    const float* b1_2 = (const float*)d_in[6];
    const float* W2_2 = (const float*)d_in[7];
    const float* b2_2 = (const float*)d_in[8];
    const float* W1_1 = (const float*)d_in[9];
    const float* b1_1 = (const float*)d_in[10];
    const float* W2_1 = (const float*)d_in[11];
    const float* b2_1 = (const float*)d_in[12];

    w2_split_kernel<<<NJOINT * 16, 256>>>(W2_3, W2_2, W2_1);

    dim3 grid(BT / MT, NJOINT);   // 98 x 43
    me_hmma_kernel<<<grid, 256, SMEM_TOTAL>>>(
        x, W1_3, b1_3, b2_3,
        W1_2, b1_2, b2_2,
        W1_1, b1_1, b2_1,
        (float*)d_out);
}